// round 1
// baseline (speedup 1.0000x reference)
#include <cuda_runtime.h>
#include <cstdint>

#define NUU 200000
#define NII 100000
#define DD  128
#define HH  128

// ---------------- scratch (static device globals; no allocation) ----------------
__device__ float g_agg_user[(size_t)NUU * DD];   // sum of x_item rows per user
__device__ float g_agg_item[(size_t)NII * DD];   // sum of x_user rows per item
__device__ int   g_cnt_user[NUU];
__device__ int   g_cnt_item[NII];
__device__ float g_Wu[2 * DD * HH];              // [Wl_iu@W_user ; Wr_iu@W_user]  (256x128)
__device__ float g_Wi[2 * DD * HH];              // [Wl_ui@W_item ; Wr_ui@W_item]
__device__ float g_cu[HH];                       // bl_iu@W_user + b_user
__device__ float g_ci[HH];                       // bl_ui@W_item + b_item

// ---------------- zero scratch ----------------
__global__ void zero_kernel() {
    size_t i = (size_t)blockIdx.x * blockDim.x + threadIdx.x;
    size_t stride = (size_t)gridDim.x * blockDim.x;
    const size_t n1 = (size_t)NUU * DD / 4;
    const size_t n2 = (size_t)NII * DD / 4;
    float4 z = make_float4(0.f, 0.f, 0.f, 0.f);
    float4* au = reinterpret_cast<float4*>(g_agg_user);
    float4* ai = reinterpret_cast<float4*>(g_agg_item);
    for (size_t p = i; p < n1; p += stride) au[p] = z;
    for (size_t p = i; p < n2; p += stride) ai[p] = z;
    for (size_t p = i; p < NUU; p += stride) g_cnt_user[p] = 0;
    for (size_t p = i; p < NII; p += stride) g_cnt_item[p] = 0;
}

// ---------------- combine weights: O = L @ R  (all 128x128 row-major) ----------------
__global__ void combine_w(const float* __restrict__ WlIU, const float* __restrict__ WrIU,
                          const float* __restrict__ WlUI, const float* __restrict__ WrUI,
                          const float* __restrict__ Wuser, const float* __restrict__ Witem) {
    int row = blockIdx.x;          // 0..127
    int mat = blockIdx.y;          // 0..3
    int j = threadIdx.x;           // 0..127
    const float* L; const float* R; float* O;
    if (mat == 0)      { L = WlIU; R = Wuser; O = g_Wu + (size_t)row * HH; }
    else if (mat == 1) { L = WrIU; R = Wuser; O = g_Wu + (size_t)(DD + row) * HH; }
    else if (mat == 2) { L = WlUI; R = Witem; O = g_Wi + (size_t)row * HH; }
    else               { L = WrUI; R = Witem; O = g_Wi + (size_t)(DD + row) * HH; }
    float s = 0.f;
#pragma unroll 8
    for (int k = 0; k < DD; k++) s += L[row * DD + k] * R[k * HH + j];
    O[j] = s;
}

__global__ void combine_c(const float* __restrict__ blIU, const float* __restrict__ bUser,
                          const float* __restrict__ blUI, const float* __restrict__ bItem,
                          const float* __restrict__ Wuser, const float* __restrict__ Witem) {
    int j = threadIdx.x;
    if (blockIdx.x == 0) {
        float s = bUser[j];
#pragma unroll 8
        for (int k = 0; k < DD; k++) s += blIU[k] * Wuser[k * HH + j];
        g_cu[j] = s;
    } else {
        float s = bItem[j];
#pragma unroll 8
        for (int k = 0; k < DD; k++) s += blUI[k] * Witem[k * HH + j];
        g_ci[j] = s;
    }
}

// ---------------- edge scatter: one warp per edge, vectorized global reductions ----------------
__global__ void edge_scatter(const float* __restrict__ xsrc, const int* __restrict__ src,
                             const int* __restrict__ dst, float* __restrict__ agg,
                             int* __restrict__ cnt, int ne) {
    int t = blockIdx.x * blockDim.x + threadIdx.x;
    int w = t >> 5;
    int lane = t & 31;
    if (w >= ne) return;
    int s = __ldg(src + w);
    int d = __ldg(dst + w);
    float4 v = *reinterpret_cast<const float4*>(xsrc + (size_t)s * DD + lane * 4);
    float* ap = agg + (size_t)d * DD + lane * 4;
    asm volatile("red.global.add.v4.f32 [%0], {%1,%2,%3,%4};"
                 :: "l"(ap), "f"(v.x), "f"(v.y), "f"(v.z), "f"(v.w) : "memory");
    if (lane == 0) atomicAdd(cnt + d, 1);
}

// ---------------- fused node GEMM:
// out[m, :] = relu( (agg[m,:]/max(cnt,1)) @ W[0:128,:] + xself[m,:] @ W[128:256,:] + cvec )
// Block tile 128x128, K=256 (two sources), 256 threads, 8x8 per thread.
__global__ __launch_bounds__(256, 2)
void node_gemm(const float* __restrict__ agg, const int* __restrict__ cnt,
               const float* __restrict__ xself, const float* __restrict__ W,
               const float* __restrict__ cvec, float* __restrict__ out, int M) {
    __shared__ float As[16][132];   // k-major, padded for aligned float4 + banks
    __shared__ float Bs[16][128];

    int tid = threadIdx.x;
    int tx = tid & 15;
    int ty = tid >> 4;
    int rowBase = blockIdx.x * 128;

    // A-loader geometry (fixed per thread): each thread loads rows r0, r0+64, 4 k's
    int r0 = tid >> 2;
    int r1 = r0 + 64;
    int kg = (tid & 3) * 4;
    int g0 = rowBase + r0, g1 = rowBase + r1;
    bool v0 = g0 < M, v1 = g1 < M;
    float inv0 = v0 ? 1.0f / (float)max(__ldg(cnt + (v0 ? g0 : 0)), 1) : 0.f;
    float inv1 = v1 ? 1.0f / (float)max(__ldg(cnt + (v1 ? g1 : 0)), 1) : 0.f;

    // B-loader geometry
    int bk = tid >> 5;            // 0..7
    int bn = (tid & 31) * 4;      // 0..124

    float acc[8][8];
#pragma unroll
    for (int i = 0; i < 8; i++)
#pragma unroll
        for (int j = 0; j < 8; j++) acc[i][j] = 0.f;

    for (int kt = 0; kt < 256; kt += 16) {
        bool scaled = (kt < 128);
        const float* src = scaled ? agg : xself;
        int ks = scaled ? kt : (kt - 128);

        float4 a0 = make_float4(0.f, 0.f, 0.f, 0.f);
        float4 a1 = a0;
        if (v0) a0 = *reinterpret_cast<const float4*>(src + (size_t)g0 * 128 + ks + kg);
        if (v1) a1 = *reinterpret_cast<const float4*>(src + (size_t)g1 * 128 + ks + kg);
        if (scaled) {
            a0.x *= inv0; a0.y *= inv0; a0.z *= inv0; a0.w *= inv0;
            a1.x *= inv1; a1.y *= inv1; a1.z *= inv1; a1.w *= inv1;
        }
        As[kg + 0][r0] = a0.x; As[kg + 1][r0] = a0.y; As[kg + 2][r0] = a0.z; As[kg + 3][r0] = a0.w;
        As[kg + 0][r1] = a1.x; As[kg + 1][r1] = a1.y; As[kg + 2][r1] = a1.z; As[kg + 3][r1] = a1.w;

        *reinterpret_cast<float4*>(&Bs[bk][bn]) =
            *reinterpret_cast<const float4*>(W + (size_t)(kt + bk) * 128 + bn);
        *reinterpret_cast<float4*>(&Bs[bk + 8][bn]) =
            *reinterpret_cast<const float4*>(W + (size_t)(kt + bk + 8) * 128 + bn);

        __syncthreads();

#pragma unroll
        for (int k = 0; k < 16; k++) {
            float4 aA = *reinterpret_cast<const float4*>(&As[k][ty * 8]);
            float4 aB = *reinterpret_cast<const float4*>(&As[k][ty * 8 + 4]);
            float4 bA = *reinterpret_cast<const float4*>(&Bs[k][tx * 8]);
            float4 bB = *reinterpret_cast<const float4*>(&Bs[k][tx * 8 + 4]);
            float a[8] = {aA.x, aA.y, aA.z, aA.w, aB.x, aB.y, aB.z, aB.w};
            float b[8] = {bA.x, bA.y, bA.z, bA.w, bB.x, bB.y, bB.z, bB.w};
#pragma unroll
            for (int i = 0; i < 8; i++)
#pragma unroll
                for (int j = 0; j < 8; j++) acc[i][j] = fmaf(a[i], b[j], acc[i][j]);
        }
        __syncthreads();
    }

    float cv[8];
#pragma unroll
    for (int j = 0; j < 8; j++) cv[j] = __ldg(cvec + tx * 8 + j);

#pragma unroll
    for (int i = 0; i < 8; i++) {
        int gr = rowBase + ty * 8 + i;
        if (gr < M) {
            float4 o0, o1;
            o0.x = fmaxf(acc[i][0] + cv[0], 0.f);
            o0.y = fmaxf(acc[i][1] + cv[1], 0.f);
            o0.z = fmaxf(acc[i][2] + cv[2], 0.f);
            o0.w = fmaxf(acc[i][3] + cv[3], 0.f);
            o1.x = fmaxf(acc[i][4] + cv[4], 0.f);
            o1.y = fmaxf(acc[i][5] + cv[5], 0.f);
            o1.z = fmaxf(acc[i][6] + cv[6], 0.f);
            o1.w = fmaxf(acc[i][7] + cv[7], 0.f);
            *reinterpret_cast<float4*>(out + (size_t)gr * 128 + tx * 8)     = o0;
            *reinterpret_cast<float4*>(out + (size_t)gr * 128 + tx * 8 + 4) = o1;
        }
    }
}

// ---------------- host launch ----------------
extern "C" void kernel_launch(void* const* d_in, const int* in_sizes, int n_in,
                              void* d_out, int out_size) {
    const float* x_user = (const float*)d_in[0];
    const float* x_item = (const float*)d_in[1];
    const int* esrc_ui = (const int*)d_in[2];
    const int* edst_ui = (const int*)d_in[3];
    const int* esrc_iu = (const int*)d_in[4];
    const int* edst_iu = (const int*)d_in[5];
    const float* Wl_ui = (const float*)d_in[6];
    const float* bl_ui = (const float*)d_in[7];
    const float* Wr_ui = (const float*)d_in[8];
    const float* Wl_iu = (const float*)d_in[9];
    const float* bl_iu = (const float*)d_in[10];
    const float* Wr_iu = (const float*)d_in[11];
    const float* W_user = (const float*)d_in[12];
    const float* b_user = (const float*)d_in[13];
    const float* W_item = (const float*)d_in[14];
    const float* b_item = (const float*)d_in[15];
    float* out = (float*)d_out;

    int ne_ui = in_sizes[2];
    int ne_iu = in_sizes[4];

    // device symbol addresses (host API, not a stream op; safe during capture)
    void *p_agg_user, *p_agg_item, *p_cnt_user, *p_cnt_item, *p_Wu, *p_Wi, *p_cu, *p_ci;
    cudaGetSymbolAddress(&p_agg_user, g_agg_user);
    cudaGetSymbolAddress(&p_agg_item, g_agg_item);
    cudaGetSymbolAddress(&p_cnt_user, g_cnt_user);
    cudaGetSymbolAddress(&p_cnt_item, g_cnt_item);
    cudaGetSymbolAddress(&p_Wu, g_Wu);
    cudaGetSymbolAddress(&p_Wi, g_Wi);
    cudaGetSymbolAddress(&p_cu, g_cu);
    cudaGetSymbolAddress(&p_ci, g_ci);

    zero_kernel<<<2048, 256>>>();

    dim3 gw(128, 4);
    combine_w<<<gw, 128>>>(Wl_iu, Wr_iu, Wl_ui, Wr_ui, W_user, W_item);
    combine_c<<<2, 128>>>(bl_iu, b_user, bl_ui, b_item, W_user, W_item);

    // ui edges: src=user -> dst=item aggregates x_user into g_agg_item
    {
        int blocks = (ne_ui * 32 + 255) / 256;
        edge_scatter<<<blocks, 256>>>(x_user, esrc_ui, edst_ui,
                                      (float*)p_agg_item, (int*)p_cnt_item, ne_ui);
    }
    // iu edges: src=item -> dst=user aggregates x_item into g_agg_user
    {
        int blocks = (ne_iu * 32 + 255) / 256;
        edge_scatter<<<blocks, 256>>>(x_item, esrc_iu, edst_iu,
                                      (float*)p_agg_user, (int*)p_cnt_user, ne_iu);
    }

    // out_user = relu(agg_user/cnt @ Au + x_user @ Bu + cu)
    node_gemm<<<(NUU + 127) / 128, 256>>>((const float*)p_agg_user, (const int*)p_cnt_user,
                                          x_user, (const float*)p_Wu, (const float*)p_cu,
                                          out, NUU);
    // out_item rows follow user rows
    node_gemm<<<(NII + 127) / 128, 256>>>((const float*)p_agg_item, (const int*)p_cnt_item,
                                          x_item, (const float*)p_Wi, (const float*)p_ci,
                                          out + (size_t)NUU * 128, NII);
}

// round 3
// speedup vs baseline: 1.6542x; 1.6542x over previous
#include <cuda_runtime.h>
#include <cuda_bf16.h>
#include <cstdint>

#define NUU 200000
#define NII 100000

// ---------------- scratch (static device globals; no allocation) ----------------
__device__ float g_agg_user[(size_t)NUU * 128];
__device__ float g_agg_item[(size_t)NII * 128];
__device__ int   g_cnt_user[NUU];
__device__ int   g_cnt_item[NII];
// combined weights, transposed to [N=128][K=256], split into bf16 hi/lo
__device__ __nv_bfloat16 g_WuT_hi[128 * 256];
__device__ __nv_bfloat16 g_WuT_lo[128 * 256];
__device__ __nv_bfloat16 g_WiT_hi[128 * 256];
__device__ __nv_bfloat16 g_WiT_lo[128 * 256];
__device__ float g_cu[128];
__device__ float g_ci[128];

__device__ __forceinline__ uint32_t smem_u32(const void* p) {
    uint32_t a;
    asm("{ .reg .u64 t; cvta.to.shared.u64 t, %1; cvt.u32.u64 %0, t; }" : "=r"(a) : "l"(p));
    return a;
}

// ---------------- zero scratch ----------------
__global__ void zero_kernel() {
    size_t i = (size_t)blockIdx.x * blockDim.x + threadIdx.x;
    size_t stride = (size_t)gridDim.x * blockDim.x;
    const size_t n1 = (size_t)NUU * 128 / 4;
    const size_t n2 = (size_t)NII * 128 / 4;
    float4 z = make_float4(0.f, 0.f, 0.f, 0.f);
    float4* au = reinterpret_cast<float4*>(g_agg_user);
    float4* ai = reinterpret_cast<float4*>(g_agg_item);
    for (size_t p = i; p < n1; p += stride) au[p] = z;
    for (size_t p = i; p < n2; p += stride) ai[p] = z;
    for (size_t p = i; p < NUU; p += stride) g_cnt_user[p] = 0;
    for (size_t p = i; p < NII; p += stride) g_cnt_item[p] = 0;
}

// ---------------- combine weights: O = L @ R, write transposed bf16 hi/lo ----------------
__global__ void combine_w(const float* __restrict__ WlIU, const float* __restrict__ WrIU,
                          const float* __restrict__ WlUI, const float* __restrict__ WrUI,
                          const float* __restrict__ Wuser, const float* __restrict__ Witem) {
    int row = blockIdx.x;          // k-row within the 128x128 product
    int mat = blockIdx.y;          // 0..3
    int j = threadIdx.x;           // n
    const float* L; const float* R;
    if (mat == 0)      { L = WlIU; R = Wuser; }
    else if (mat == 1) { L = WrIU; R = Wuser; }
    else if (mat == 2) { L = WlUI; R = Witem; }
    else               { L = WrUI; R = Witem; }
    float s = 0.f;
#pragma unroll 8
    for (int k = 0; k < 128; k++) s += L[row * 128 + k] * R[k * 128 + j];
    int gk = (mat & 1) ? (128 + row) : row;
    __nv_bfloat16* Th = (mat < 2) ? g_WuT_hi : g_WiT_hi;
    __nv_bfloat16* Tl = (mat < 2) ? g_WuT_lo : g_WiT_lo;
    __nv_bfloat16 h = __float2bfloat16_rn(s);
    float r = s - __bfloat162float(h);
    Th[(size_t)j * 256 + gk] = h;
    Tl[(size_t)j * 256 + gk] = __float2bfloat16_rn(r);
}

__global__ void combine_c(const float* __restrict__ blIU, const float* __restrict__ bUser,
                          const float* __restrict__ blUI, const float* __restrict__ bItem,
                          const float* __restrict__ Wuser, const float* __restrict__ Witem) {
    int j = threadIdx.x;
    if (blockIdx.x == 0) {
        float s = bUser[j];
#pragma unroll 8
        for (int k = 0; k < 128; k++) s += blIU[k] * Wuser[k * 128 + j];
        g_cu[j] = s;
    } else {
        float s = bItem[j];
#pragma unroll 8
        for (int k = 0; k < 128; k++) s += blUI[k] * Witem[k * 128 + j];
        g_ci[j] = s;
    }
}

// ---------------- edge scatter: one warp per edge, vectorized global reductions ----------------
__global__ void edge_scatter(const float* __restrict__ xsrc, const int* __restrict__ src,
                             const int* __restrict__ dst, float* __restrict__ agg,
                             int* __restrict__ cnt, int ne) {
    int t = blockIdx.x * blockDim.x + threadIdx.x;
    int w = t >> 5;
    int lane = t & 31;
    if (w >= ne) return;
    int s = __ldg(src + w);
    int d = __ldg(dst + w);
    float4 v = *reinterpret_cast<const float4*>(xsrc + (size_t)s * 128 + lane * 4);
    float* ap = agg + (size_t)d * 128 + lane * 4;
    asm volatile("red.global.add.v4.f32 [%0], {%1,%2,%3,%4};"
                 :: "l"(ap), "f"(v.x), "f"(v.y), "f"(v.z), "f"(v.w) : "memory");
    if (lane == 0) atomicAdd(cnt + d, 1);
}

// ---------------- mma.sync fused node GEMM ----------------
// out[m,:] = relu( (agg[m,:]/max(cnt,1)) @ W[0:128,:] + xself[m,:] @ W[128:256,:] + cvec )
// A = [agg | xself] (K=256, bf16 hi/lo split), B = WT [N=128][K=256] bf16 hi/lo.
// CTA tile 128x128, 8 warps (each 64m x 32n), K-chunks of 64, HMMA m16n8k16.
#define SM_INV  0u
#define SM_AHI  1024u
#define SM_ALO  (SM_AHI + 16384u)
#define SM_BHI  (SM_ALO + 16384u)
#define SM_BLO  (SM_BHI + 16384u)
#define SM_TOTAL (SM_BLO + 16384u)

__device__ __forceinline__ void ldsm4(uint32_t& r0, uint32_t& r1, uint32_t& r2, uint32_t& r3,
                                      uint32_t addr) {
    asm volatile("ldmatrix.sync.aligned.m8n8.x4.shared.b16 {%0,%1,%2,%3}, [%4];"
                 : "=r"(r0), "=r"(r1), "=r"(r2), "=r"(r3) : "r"(addr));
}
__device__ __forceinline__ void mma16816(float* c, uint32_t a0, uint32_t a1, uint32_t a2,
                                         uint32_t a3, uint32_t b0, uint32_t b1) {
    asm volatile("mma.sync.aligned.m16n8k16.row.col.f32.bf16.bf16.f32 "
                 "{%0,%1,%2,%3}, {%4,%5,%6,%7}, {%8,%9}, {%0,%1,%2,%3};"
                 : "+f"(c[0]), "+f"(c[1]), "+f"(c[2]), "+f"(c[3])
                 : "r"(a0), "r"(a1), "r"(a2), "r"(a3), "r"(b0), "r"(b1));
}

__global__ __launch_bounds__(256, 2)
void node_gemm_mma(const float* __restrict__ agg, const int* __restrict__ cnt,
                   const float* __restrict__ xself,
                   const __nv_bfloat16* __restrict__ WTh, const __nv_bfloat16* __restrict__ WTl,
                   const float* __restrict__ cvec, float* __restrict__ out, int M) {
    extern __shared__ char smem[];
    const uint32_t sb = smem_u32(smem);
    const int tid = threadIdx.x;
    const int wid = tid >> 5;
    const int lane = tid & 31;
    const int rowBase = blockIdx.x * 128;

    float* s_inv = reinterpret_cast<float*>(smem + SM_INV);
    if (tid < 128) {
        int gr = rowBase + tid;
        int c = (gr < M) ? __ldg(cnt + gr) : 1;
        s_inv[tid] = 1.0f / (float)max(c, 1);
    }
    __syncthreads();

    // warp tile: m-half mw (64 rows), n-quarter nw (32 cols)
    const int mw = wid & 1;
    const int nw = wid >> 1;

    // lane-invariant ldmatrix address parts
    const int laneRowA = mw * 64 + (lane & 15);
    const uint32_t cAxor = (uint32_t)(laneRowA & 7) << 4;
    const uint32_t aRowByte = (uint32_t)laneRowA * 128;
    const uint32_t kLaneByte = (uint32_t)(lane >> 4) * 16;

    uint32_t bRowByte[2], cBxor[2];
#pragma unroll
    for (int nt2 = 0; nt2 < 2; nt2++) {
        int rn = nw * 32 + nt2 * 16 + (lane & 15);
        bRowByte[nt2] = (uint32_t)rn * 128;
        cBxor[nt2] = (uint32_t)(rn & 7) << 4;
    }

    float acc[4][4][4];
#pragma unroll
    for (int i = 0; i < 4; i++)
#pragma unroll
        for (int j = 0; j < 4; j++)
#pragma unroll
            for (int r = 0; r < 4; r++) acc[i][j][r] = 0.f;

    for (int c = 0; c < 4; c++) {
        const float* srcA = (c < 2) ? agg : xself;
        const int koff = (c & 1) * 64;
        const int cK = c * 64;
        const bool scaled = (c < 2);
        if (c > 0) __syncthreads();
        // ---- stage A (fp32 -> bf16 hi/lo, scaled) and B (bf16 copy), swizzled ----
#pragma unroll
        for (int i = 0; i < 4; i++) {
            int g = tid + i * 256;           // 0..1023
            int row = g >> 3;                // 0..127
            int k8 = (g & 7) * 8;            // 0..56
            int gr = rowBase + row;
            float4 f0 = make_float4(0.f, 0.f, 0.f, 0.f), f1 = f0;
            if (gr < M) {
                f0 = *reinterpret_cast<const float4*>(srcA + (size_t)gr * 128 + koff + k8);
                f1 = *reinterpret_cast<const float4*>(srcA + (size_t)gr * 128 + koff + k8 + 4);
            }
            float sc = scaled ? s_inv[row] : 1.0f;
            float v[8] = {f0.x * sc, f0.y * sc, f0.z * sc, f0.w * sc,
                          f1.x * sc, f1.y * sc, f1.z * sc, f1.w * sc};
            uint32_t hw[4], lw[4];
#pragma unroll
            for (int j = 0; j < 4; j++) {
                __nv_bfloat16 h0 = __float2bfloat16_rn(v[2 * j]);
                __nv_bfloat16 h1 = __float2bfloat16_rn(v[2 * j + 1]);
                __nv_bfloat16 l0 = __float2bfloat16_rn(v[2 * j] - __bfloat162float(h0));
                __nv_bfloat16 l1 = __float2bfloat16_rn(v[2 * j + 1] - __bfloat162float(h1));
                __nv_bfloat162 hp; hp.x = h0; hp.y = h1;
                __nv_bfloat162 lp; lp.x = l0; lp.y = l1;
                hw[j] = *reinterpret_cast<uint32_t*>(&hp);
                lw[j] = *reinterpret_cast<uint32_t*>(&lp);
            }
            uint32_t sw = (uint32_t)row * 128 + (((uint32_t)k8 * 2) ^ ((uint32_t)(row & 7) << 4));
            *reinterpret_cast<uint4*>(smem + SM_AHI + sw) = make_uint4(hw[0], hw[1], hw[2], hw[3]);
            *reinterpret_cast<uint4*>(smem + SM_ALO + sw) = make_uint4(lw[0], lw[1], lw[2], lw[3]);
            uint4 bh = *reinterpret_cast<const uint4*>(WTh + (size_t)row * 256 + cK + k8);
            uint4 bl = *reinterpret_cast<const uint4*>(WTl + (size_t)row * 256 + cK + k8);
            *reinterpret_cast<uint4*>(smem + SM_BHI + sw) = bh;
            *reinterpret_cast<uint4*>(smem + SM_BLO + sw) = bl;
        }
        __syncthreads();

        // ---- compute: 4 k16 steps ----
#pragma unroll
        for (int ks = 0; ks < 4; ks++) {
            uint32_t kb = (uint32_t)ks * 32 + kLaneByte;   // bytes within 128B row, bits 4-6
            // B fragments: 4 n8-tiles, hi & lo
            uint32_t bh[4][2], bl[4][2];
#pragma unroll
            for (int nt2 = 0; nt2 < 2; nt2++) {
                uint32_t r0, r1, r2, r3;
                ldsm4(r0, r1, r2, r3, sb + SM_BHI + bRowByte[nt2] + (kb ^ cBxor[nt2]));
                bh[nt2 * 2][0] = r0; bh[nt2 * 2][1] = r2;
                bh[nt2 * 2 + 1][0] = r1; bh[nt2 * 2 + 1][1] = r3;
                ldsm4(r0, r1, r2, r3, sb + SM_BLO + bRowByte[nt2] + (kb ^ cBxor[nt2]));
                bl[nt2 * 2][0] = r0; bl[nt2 * 2][1] = r2;
                bl[nt2 * 2 + 1][0] = r1; bl[nt2 * 2 + 1][1] = r3;
            }
#pragma unroll
            for (int mt = 0; mt < 4; mt++) {
                uint32_t ah0, ah1, ah2, ah3, al0, al1, al2, al3;
                uint32_t abase = sb + aRowByte + (uint32_t)mt * 2048 + (kb ^ cAxor);
                ldsm4(ah0, ah1, ah2, ah3, abase + SM_AHI);
                ldsm4(al0, al1, al2, al3, abase + SM_ALO);
#pragma unroll
                for (int nt = 0; nt < 4; nt++) {
                    mma16816(acc[mt][nt], ah0, ah1, ah2, ah3, bh[nt][0], bh[nt][1]);
                    mma16816(acc[mt][nt], ah0, ah1, ah2, ah3, bl[nt][0], bl[nt][1]);
                    mma16816(acc[mt][nt], al0, al1, al2, al3, bh[nt][0], bh[nt][1]);
                }
            }
        }
    }

    // ---- epilogue: bias + relu + store ----
    float cb[4][2];
#pragma unroll
    for (int nt = 0; nt < 4; nt++) {
        int col = nw * 32 + nt * 8 + (lane & 3) * 2;
        cb[nt][0] = __ldg(cvec + col);
        cb[nt][1] = __ldg(cvec + col + 1);
    }
#pragma unroll
    for (int mt = 0; mt < 4; mt++) {
        int r0 = rowBase + mw * 64 + mt * 16 + (lane >> 2);
        int r1 = r0 + 8;
#pragma unroll
        for (int nt = 0; nt < 4; nt++) {
            int col = nw * 32 + nt * 8 + (lane & 3) * 2;
            if (r0 < M) {
                float2 o;
                o.x = fmaxf(acc[mt][nt][0] + cb[nt][0], 0.f);
                o.y = fmaxf(acc[mt][nt][1] + cb[nt][1], 0.f);
                *reinterpret_cast<float2*>(out + (size_t)r0 * 128 + col) = o;
            }
            if (r1 < M) {
                float2 o;
                o.x = fmaxf(acc[mt][nt][2] + cb[nt][0], 0.f);
                o.y = fmaxf(acc[mt][nt][3] + cb[nt][1], 0.f);
                *reinterpret_cast<float2*>(out + (size_t)r1 * 128 + col) = o;
            }
        }
    }
}

// ---------------- host launch ----------------
extern "C" void kernel_launch(void* const* d_in, const int* in_sizes, int n_in,
                              void* d_out, int out_size) {
    const float* x_user = (const float*)d_in[0];
    const float* x_item = (const float*)d_in[1];
    const int* esrc_ui = (const int*)d_in[2];
    const int* edst_ui = (const int*)d_in[3];
    const int* esrc_iu = (const int*)d_in[4];
    const int* edst_iu = (const int*)d_in[5];
    const float* Wl_ui = (const float*)d_in[6];
    const float* bl_ui = (const float*)d_in[7];
    const float* Wr_ui = (const float*)d_in[8];
    const float* Wl_iu = (const float*)d_in[9];
    const float* bl_iu = (const float*)d_in[10];
    const float* Wr_iu = (const float*)d_in[11];
    const float* W_user = (const float*)d_in[12];
    const float* b_user = (const float*)d_in[13];
    const float* W_item = (const float*)d_in[14];
    const float* b_item = (const float*)d_in[15];
    float* out = (float*)d_out;

    int ne_ui = in_sizes[2];
    int ne_iu = in_sizes[4];

    void *p_agg_user, *p_agg_item, *p_cnt_user, *p_cnt_item;
    void *p_Wuh, *p_Wul, *p_Wih, *p_Wil, *p_cu, *p_ci;
    cudaGetSymbolAddress(&p_agg_user, g_agg_user);
    cudaGetSymbolAddress(&p_agg_item, g_agg_item);
    cudaGetSymbolAddress(&p_cnt_user, g_cnt_user);
    cudaGetSymbolAddress(&p_cnt_item, g_cnt_item);
    cudaGetSymbolAddress(&p_Wuh, g_WuT_hi);
    cudaGetSymbolAddress(&p_Wul, g_WuT_lo);
    cudaGetSymbolAddress(&p_Wih, g_WiT_hi);
    cudaGetSymbolAddress(&p_Wil, g_WiT_lo);
    cudaGetSymbolAddress(&p_cu, g_cu);
    cudaGetSymbolAddress(&p_ci, g_ci);

    cudaFuncSetAttribute(node_gemm_mma, cudaFuncAttributeMaxDynamicSharedMemorySize, SM_TOTAL);

    zero_kernel<<<2048, 256>>>();

    dim3 gw(128, 4);
    combine_w<<<gw, 128>>>(Wl_iu, Wr_iu, Wl_ui, Wr_ui, W_user, W_item);
    combine_c<<<2, 128>>>(bl_iu, b_user, bl_ui, b_item, W_user, W_item);

    {
        int blocks = (ne_ui * 32 + 255) / 256;
        edge_scatter<<<blocks, 256>>>(x_user, esrc_ui, edst_ui,
                                      (float*)p_agg_item, (int*)p_cnt_item, ne_ui);
    }
    {
        int blocks = (ne_iu * 32 + 255) / 256;
        edge_scatter<<<blocks, 256>>>(x_item, esrc_iu, edst_iu,
                                      (float*)p_agg_user, (int*)p_cnt_user, ne_iu);
    }

    node_gemm_mma<<<(NUU + 127) / 128, 256, SM_TOTAL>>>(
        (const float*)p_agg_user, (const int*)p_cnt_user, x_user,
        (const __nv_bfloat16*)p_Wuh, (const __nv_bfloat16*)p_Wul,
        (const float*)p_cu, out, NUU);
    node_gemm_mma<<<(NII + 127) / 128, 256, SM_TOTAL>>>(
        (const float*)p_agg_item, (const int*)p_cnt_item, x_item,
        (const __nv_bfloat16*)p_Wih, (const __nv_bfloat16*)p_Wil,
        (const float*)p_ci, out + (size_t)NUU * 128, NII);
}

// round 4
// speedup vs baseline: 1.9294x; 1.1663x over previous
#include <cuda_runtime.h>
#include <cuda_bf16.h>
#include <cstdint>

#define NUU 200000
#define NII 100000
#define NT  (NUU + NII)
#define NBLK ((NT + 1023) / 1024)   // 293

// ---------------- scratch (static device globals; no allocation) ----------------
__device__ __nv_bfloat16 g_aggh[(size_t)NT * 128];   // mean-aggregated neighbors, bf16 hi
__device__ __nv_bfloat16 g_aggl[(size_t)NT * 128];   // bf16 residual (lo)
__device__ int g_cnt[NT];
__device__ int g_off[NT + 1];
__device__ int g_cur[NT];
__device__ int g_bsum[1024];
__device__ int g_nbr[1200000 + 64];
// combined weights, transposed to [N=128][K=256], bf16 hi/lo
__device__ __nv_bfloat16 g_WuT_hi[128 * 256];
__device__ __nv_bfloat16 g_WuT_lo[128 * 256];
__device__ __nv_bfloat16 g_WiT_hi[128 * 256];
__device__ __nv_bfloat16 g_WiT_lo[128 * 256];
__device__ float g_cu[128];
__device__ float g_ci[128];

__device__ __forceinline__ uint32_t smem_u32(const void* p) {
    uint32_t a;
    asm("{ .reg .u64 t; cvta.to.shared.u64 t, %1; cvt.u32.u64 %0, t; }" : "=r"(a) : "l"(p));
    return a;
}
__device__ __forceinline__ void cpa16(uint32_t d, const void* s) {
    asm volatile("cp.async.cg.shared.global [%0], [%1], 16;" :: "r"(d), "l"(s));
}
#define CP_COMMIT() asm volatile("cp.async.commit_group;" ::: "memory")
#define CP_WAIT0()  asm volatile("cp.async.wait_group 0;" ::: "memory")

// ---------------- CSR build ----------------
__global__ void zero_cnt() {
    int i = blockIdx.x * blockDim.x + threadIdx.x;
    if (i < NT) g_cnt[i] = 0;
}
__global__ void hist_k(const int* __restrict__ dst, int ne, int base) {
    int i = blockIdx.x * blockDim.x + threadIdx.x;
    if (i < ne) atomicAdd(&g_cnt[base + dst[i]], 1);
}
__global__ void scan1() {
    __shared__ int sh[1024];
    int t = threadIdx.x;
    int idx = blockIdx.x * 1024 + t;
    int c = (idx < NT) ? g_cnt[idx] : 0;
    sh[t] = c;
    __syncthreads();
#pragma unroll
    for (int o = 1; o < 1024; o <<= 1) {
        int v = (t >= o) ? sh[t - o] : 0;
        __syncthreads();
        sh[t] += v;
        __syncthreads();
    }
    if (idx < NT) g_off[idx] = sh[t] - c;           // local exclusive
    if (t == 1023) g_bsum[blockIdx.x] = sh[1023];   // block total
}
__global__ void scan2() {
    __shared__ int sh[512];
    int t = threadIdx.x;
    int c = (t < NBLK) ? g_bsum[t] : 0;
    sh[t] = c;
    __syncthreads();
#pragma unroll
    for (int o = 1; o < 512; o <<= 1) {
        int v = (t >= o) ? sh[t - o] : 0;
        __syncthreads();
        sh[t] += v;
        __syncthreads();
    }
    if (t < NBLK) g_bsum[t] = sh[t] - c;            // exclusive block base
}
__global__ void scan3(int totE) {
    int t = threadIdx.x;
    int idx = blockIdx.x * 1024 + t;
    if (idx < NT) {
        int v = g_off[idx] + g_bsum[blockIdx.x];
        g_off[idx] = v;
        g_cur[idx] = v;
    }
    if (idx == 0) g_off[NT] = totE;
}
__global__ void fill_k(const int* __restrict__ src, const int* __restrict__ dst,
                       int ne, int base) {
    int i = blockIdx.x * blockDim.x + threadIdx.x;
    if (i < ne) {
        int p = atomicAdd(&g_cur[base + dst[i]], 1);
        g_nbr[p] = src[i];
    }
}

// ---------------- gather: one warp per dst node, mean -> bf16 hi/lo ----------------
__global__ void gather_k(const float* __restrict__ x_user, const float* __restrict__ x_item) {
    int w = (blockIdx.x * blockDim.x + threadIdx.x) >> 5;
    int lane = threadIdx.x & 31;
    if (w >= NT) return;
    const float* xs = (w < NUU) ? x_item : x_user;  // users aggregate items, items users
    int o = g_off[w], e = g_off[w + 1];
    float a0 = 0.f, a1 = 0.f, a2 = 0.f, a3 = 0.f;
    int p = o;
    for (; p + 1 < e; p += 2) {
        int s0 = __ldg(&g_nbr[p]);
        int s1 = __ldg(&g_nbr[p + 1]);
        float4 v0 = *reinterpret_cast<const float4*>(xs + (size_t)s0 * 128 + lane * 4);
        float4 v1 = *reinterpret_cast<const float4*>(xs + (size_t)s1 * 128 + lane * 4);
        a0 += v0.x + v1.x; a1 += v0.y + v1.y; a2 += v0.z + v1.z; a3 += v0.w + v1.w;
    }
    if (p < e) {
        int s0 = __ldg(&g_nbr[p]);
        float4 v0 = *reinterpret_cast<const float4*>(xs + (size_t)s0 * 128 + lane * 4);
        a0 += v0.x; a1 += v0.y; a2 += v0.z; a3 += v0.w;
    }
    float inv = 1.0f / (float)max(e - o, 1);
    a0 *= inv; a1 *= inv; a2 *= inv; a3 *= inv;
    __nv_bfloat16 h0 = __float2bfloat16_rn(a0), h1 = __float2bfloat16_rn(a1);
    __nv_bfloat16 h2 = __float2bfloat16_rn(a2), h3 = __float2bfloat16_rn(a3);
    __nv_bfloat16 l0 = __float2bfloat16_rn(a0 - __bfloat162float(h0));
    __nv_bfloat16 l1 = __float2bfloat16_rn(a1 - __bfloat162float(h1));
    __nv_bfloat16 l2 = __float2bfloat16_rn(a2 - __bfloat162float(h2));
    __nv_bfloat16 l3 = __float2bfloat16_rn(a3 - __bfloat162float(h3));
    __nv_bfloat162 hp0; hp0.x = h0; hp0.y = h1;
    __nv_bfloat162 hp1; hp1.x = h2; hp1.y = h3;
    __nv_bfloat162 lp0; lp0.x = l0; lp0.y = l1;
    __nv_bfloat162 lp1; lp1.x = l2; lp1.y = l3;
    uint2 hw = make_uint2(*reinterpret_cast<uint32_t*>(&hp0), *reinterpret_cast<uint32_t*>(&hp1));
    uint2 lw = make_uint2(*reinterpret_cast<uint32_t*>(&lp0), *reinterpret_cast<uint32_t*>(&lp1));
    *reinterpret_cast<uint2*>(g_aggh + (size_t)w * 128 + lane * 4) = hw;
    *reinterpret_cast<uint2*>(g_aggl + (size_t)w * 128 + lane * 4) = lw;
}

// ---------------- combine weights: O = L @ R, write transposed bf16 hi/lo ----------------
__global__ void combine_w(const float* __restrict__ WlIU, const float* __restrict__ WrIU,
                          const float* __restrict__ WlUI, const float* __restrict__ WrUI,
                          const float* __restrict__ Wuser, const float* __restrict__ Witem) {
    int row = blockIdx.x;
    int mat = blockIdx.y;
    int j = threadIdx.x;
    const float* L; const float* R;
    if (mat == 0)      { L = WlIU; R = Wuser; }
    else if (mat == 1) { L = WrIU; R = Wuser; }
    else if (mat == 2) { L = WlUI; R = Witem; }
    else               { L = WrUI; R = Witem; }
    float s = 0.f;
#pragma unroll 8
    for (int k = 0; k < 128; k++) s += L[row * 128 + k] * R[k * 128 + j];
    int gk = (mat & 1) ? (128 + row) : row;
    __nv_bfloat16* Th = (mat < 2) ? g_WuT_hi : g_WiT_hi;
    __nv_bfloat16* Tl = (mat < 2) ? g_WuT_lo : g_WiT_lo;
    __nv_bfloat16 h = __float2bfloat16_rn(s);
    float r = s - __bfloat162float(h);
    Th[(size_t)j * 256 + gk] = h;
    Tl[(size_t)j * 256 + gk] = __float2bfloat16_rn(r);
}

__global__ void combine_c(const float* __restrict__ blIU, const float* __restrict__ bUser,
                          const float* __restrict__ blUI, const float* __restrict__ bItem,
                          const float* __restrict__ Wuser, const float* __restrict__ Witem) {
    int j = threadIdx.x;
    if (blockIdx.x == 0) {
        float s = bUser[j];
#pragma unroll 8
        for (int k = 0; k < 128; k++) s += blIU[k] * Wuser[k * 128 + j];
        g_cu[j] = s;
    } else {
        float s = bItem[j];
#pragma unroll 8
        for (int k = 0; k < 128; k++) s += blUI[k] * Witem[k * 128 + j];
        g_ci[j] = s;
    }
}

// ---------------- pipelined mma.sync fused node GEMM ----------------
// out[m,:] = relu( aggMean(bf16 hi/lo)[m,:] @ W[0:128,:] + xself[m,:] @ W[128:256,:] + cvec )
// CTA 128x128, double-buffered smem, B via cp.async, A prefetched in registers.
#define BO_AH 0u
#define BO_AL 16384u
#define BO_BH 32768u
#define BO_BL 49152u
#define BUF   65536u
#define SM_TOTAL (2u * BUF)

__device__ __forceinline__ void ldsm4(uint32_t& r0, uint32_t& r1, uint32_t& r2, uint32_t& r3,
                                      uint32_t addr) {
    asm volatile("ldmatrix.sync.aligned.m8n8.x4.shared.b16 {%0,%1,%2,%3}, [%4];"
                 : "=r"(r0), "=r"(r1), "=r"(r2), "=r"(r3) : "r"(addr));
}
__device__ __forceinline__ void mma16816(float* c, uint32_t a0, uint32_t a1, uint32_t a2,
                                         uint32_t a3, uint32_t b0, uint32_t b1) {
    asm volatile("mma.sync.aligned.m16n8k16.row.col.f32.bf16.bf16.f32 "
                 "{%0,%1,%2,%3}, {%4,%5,%6,%7}, {%8,%9}, {%0,%1,%2,%3};"
                 : "+f"(c[0]), "+f"(c[1]), "+f"(c[2]), "+f"(c[3])
                 : "r"(a0), "r"(a1), "r"(a2), "r"(a3), "r"(b0), "r"(b1));
}

__global__ __launch_bounds__(256, 1)
void node_gemm_mma(const __nv_bfloat16* __restrict__ aggh, const __nv_bfloat16* __restrict__ aggl,
                   const float* __restrict__ xself,
                   const __nv_bfloat16* __restrict__ WTh, const __nv_bfloat16* __restrict__ WTl,
                   const float* __restrict__ cvec, float* __restrict__ out, int M) {
    extern __shared__ char smem[];
    const uint32_t sb = smem_u32(smem);
    const int tid = threadIdx.x;
    const int wid = tid >> 5;
    const int lane = tid & 31;
    const int rowBase = blockIdx.x * 128;

    const int mw = wid & 1;
    const int nw = wid >> 1;

    const int laneRowA = mw * 64 + (lane & 15);
    const uint32_t cAxor = (uint32_t)(laneRowA & 7) << 4;
    const uint32_t aRowByte = (uint32_t)laneRowA * 128;
    const uint32_t kLaneByte = (uint32_t)(lane >> 4) * 16;

    uint32_t bRowByte[2], cBxor[2];
#pragma unroll
    for (int nt2 = 0; nt2 < 2; nt2++) {
        int rn = nw * 32 + nt2 * 16 + (lane & 15);
        bRowByte[nt2] = (uint32_t)rn * 128;
        cBxor[nt2] = (uint32_t)(rn & 7) << 4;
    }

    float acc[4][4][4];
#pragma unroll
    for (int i = 0; i < 4; i++)
#pragma unroll
        for (int j = 0; j < 4; j++)
#pragma unroll
            for (int r = 0; r < 4; r++) acc[i][j][r] = 0.f;

    uint4 uh[4], ul[4];
    float4 fr[8];

    auto loadA_agg = [&](int koff) {
#pragma unroll
        for (int i = 0; i < 4; i++) {
            int g = tid + i * 256;
            int row = g >> 3, k8 = (g & 7) * 8;
            int gr = rowBase + row;
            if (gr < M) {
                size_t idx = (size_t)gr * 128 + koff + k8;
                uh[i] = *reinterpret_cast<const uint4*>(aggh + idx);
                ul[i] = *reinterpret_cast<const uint4*>(aggl + idx);
            } else {
                uh[i] = make_uint4(0, 0, 0, 0);
                ul[i] = make_uint4(0, 0, 0, 0);
            }
        }
    };
    auto loadA_x = [&](int koff) {
#pragma unroll
        for (int i = 0; i < 4; i++) {
            int g = tid + i * 256;
            int row = g >> 3, k8 = (g & 7) * 8;
            int gr = rowBase + row;
            if (gr < M) {
                fr[2 * i]     = *reinterpret_cast<const float4*>(xself + (size_t)gr * 128 + koff + k8);
                fr[2 * i + 1] = *reinterpret_cast<const float4*>(xself + (size_t)gr * 128 + koff + k8 + 4);
            } else {
                fr[2 * i] = make_float4(0.f, 0.f, 0.f, 0.f);
                fr[2 * i + 1] = fr[2 * i];
            }
        }
    };
    auto storeA_agg = [&](uint32_t bb) {
#pragma unroll
        for (int i = 0; i < 4; i++) {
            int g = tid + i * 256;
            int row = g >> 3, k8 = (g & 7) * 8;
            uint32_t sw = (uint32_t)row * 128 + (((uint32_t)k8 * 2) ^ ((uint32_t)(row & 7) << 4));
            *reinterpret_cast<uint4*>(smem + bb + BO_AH + sw) = uh[i];
            *reinterpret_cast<uint4*>(smem + bb + BO_AL + sw) = ul[i];
        }
    };
    auto storeA_x = [&](uint32_t bb) {
#pragma unroll
        for (int i = 0; i < 4; i++) {
            int g = tid + i * 256;
            int row = g >> 3, k8 = (g & 7) * 8;
            float v[8] = {fr[2 * i].x, fr[2 * i].y, fr[2 * i].z, fr[2 * i].w,
                          fr[2 * i + 1].x, fr[2 * i + 1].y, fr[2 * i + 1].z, fr[2 * i + 1].w};
            uint32_t hw[4], lw[4];
#pragma unroll
            for (int j = 0; j < 4; j++) {
                __nv_bfloat16 h0 = __float2bfloat16_rn(v[2 * j]);
                __nv_bfloat16 h1 = __float2bfloat16_rn(v[2 * j + 1]);
                __nv_bfloat16 l0 = __float2bfloat16_rn(v[2 * j] - __bfloat162float(h0));
                __nv_bfloat16 l1 = __float2bfloat16_rn(v[2 * j + 1] - __bfloat162float(h1));
                __nv_bfloat162 hp; hp.x = h0; hp.y = h1;
                __nv_bfloat162 lp; lp.x = l0; lp.y = l1;
                hw[j] = *reinterpret_cast<uint32_t*>(&hp);
                lw[j] = *reinterpret_cast<uint32_t*>(&lp);
            }
            uint32_t sw = (uint32_t)row * 128 + (((uint32_t)k8 * 2) ^ ((uint32_t)(row & 7) << 4));
            *reinterpret_cast<uint4*>(smem + bb + BO_AH + sw) = make_uint4(hw[0], hw[1], hw[2], hw[3]);
            *reinterpret_cast<uint4*>(smem + bb + BO_AL + sw) = make_uint4(lw[0], lw[1], lw[2], lw[3]);
        }
    };
    auto stageB = [&](uint32_t bb, int cK) {
#pragma unroll
        for (int i = 0; i < 4; i++) {
            int g = tid + i * 256;
            int row = g >> 3, k8 = (g & 7) * 8;
            uint32_t sw = (uint32_t)row * 128 + (((uint32_t)k8 * 2) ^ ((uint32_t)(row & 7) << 4));
            cpa16(sb + bb + BO_BH + sw, WTh + (size_t)row * 256 + cK + k8);
            cpa16(sb + bb + BO_BL + sw, WTl + (size_t)row * 256 + cK + k8);
        }
    };
    auto compute = [&](uint32_t bb) {
#pragma unroll
        for (int ks = 0; ks < 4; ks++) {
            uint32_t kb = (uint32_t)ks * 32 + kLaneByte;
            uint32_t bh[4][2], bl[4][2];
#pragma unroll
            for (int nt2 = 0; nt2 < 2; nt2++) {
                uint32_t r0, r1, r2, r3;
                ldsm4(r0, r1, r2, r3, sb + bb + BO_BH + bRowByte[nt2] + (kb ^ cBxor[nt2]));
                bh[nt2 * 2][0] = r0; bh[nt2 * 2][1] = r2;
                bh[nt2 * 2 + 1][0] = r1; bh[nt2 * 2 + 1][1] = r3;
                ldsm4(r0, r1, r2, r3, sb + bb + BO_BL + bRowByte[nt2] + (kb ^ cBxor[nt2]));
                bl[nt2 * 2][0] = r0; bl[nt2 * 2][1] = r2;
                bl[nt2 * 2 + 1][0] = r1; bl[nt2 * 2 + 1][1] = r3;
            }
#pragma unroll
            for (int mt = 0; mt < 4; mt++) {
                uint32_t ah0, ah1, ah2, ah3, al0, al1, al2, al3;
                uint32_t abase = sb + bb + aRowByte + (uint32_t)mt * 2048 + (kb ^ cAxor);
                ldsm4(ah0, ah1, ah2, ah3, abase + BO_AH);
                ldsm4(al0, al1, al2, al3, abase + BO_AL);
#pragma unroll
                for (int nt = 0; nt < 4; nt++) {
                    mma16816(acc[mt][nt], ah0, ah1, ah2, ah3, bh[nt][0], bh[nt][1]);
                    mma16816(acc[mt][nt], ah0, ah1, ah2, ah3, bl[nt][0], bl[nt][1]);
                    mma16816(acc[mt][nt], al0, al1, al2, al3, bh[nt][0], bh[nt][1]);
                }
            }
        }
    };

    // prologue: chunk 0 (agg k0:64) into buf0
    loadA_agg(0);
    stageB(0, 0);
    CP_COMMIT();
    storeA_agg(0);
    CP_WAIT0();
    __syncthreads();

    // c=0: prefetch chunk1 (agg k64:128) into buf1
    loadA_agg(64);
    stageB(BUF, 64);
    CP_COMMIT();
    compute(0);
    storeA_agg(BUF);
    CP_WAIT0();
    __syncthreads();

    // c=1: prefetch chunk2 (xself k0:64) into buf0
    loadA_x(0);
    stageB(0, 128);
    CP_COMMIT();
    compute(BUF);
    storeA_x(0);
    CP_WAIT0();
    __syncthreads();

    // c=2: prefetch chunk3 (xself k64:128) into buf1
    loadA_x(64);
    stageB(BUF, 192);
    CP_COMMIT();
    compute(0);
    storeA_x(BUF);
    CP_WAIT0();
    __syncthreads();

    // c=3
    compute(BUF);

    // ---- epilogue: bias + relu + store ----
    float cb[4][2];
#pragma unroll
    for (int nt = 0; nt < 4; nt++) {
        int col = nw * 32 + nt * 8 + (lane & 3) * 2;
        cb[nt][0] = __ldg(cvec + col);
        cb[nt][1] = __ldg(cvec + col + 1);
    }
#pragma unroll
    for (int mt = 0; mt < 4; mt++) {
        int r0 = rowBase + mw * 64 + mt * 16 + (lane >> 2);
        int r1 = r0 + 8;
#pragma unroll
        for (int nt = 0; nt < 4; nt++) {
            int col = nw * 32 + nt * 8 + (lane & 3) * 2;
            if (r0 < M) {
                float2 o;
                o.x = fmaxf(acc[mt][nt][0] + cb[nt][0], 0.f);
                o.y = fmaxf(acc[mt][nt][1] + cb[nt][1], 0.f);
                *reinterpret_cast<float2*>(out + (size_t)r0 * 128 + col) = o;
            }
            if (r1 < M) {
                float2 o;
                o.x = fmaxf(acc[mt][nt][2] + cb[nt][0], 0.f);
                o.y = fmaxf(acc[mt][nt][3] + cb[nt][1], 0.f);
                *reinterpret_cast<float2*>(out + (size_t)r1 * 128 + col) = o;
            }
        }
    }
}

// ---------------- host launch ----------------
extern "C" void kernel_launch(void* const* d_in, const int* in_sizes, int n_in,
                              void* d_out, int out_size) {
    const float* x_user = (const float*)d_in[0];
    const float* x_item = (const float*)d_in[1];
    const int* esrc_ui = (const int*)d_in[2];
    const int* edst_ui = (const int*)d_in[3];
    const int* esrc_iu = (const int*)d_in[4];
    const int* edst_iu = (const int*)d_in[5];
    const float* Wl_ui = (const float*)d_in[6];
    const float* bl_ui = (const float*)d_in[7];
    const float* Wr_ui = (const float*)d_in[8];
    const float* Wl_iu = (const float*)d_in[9];
    const float* bl_iu = (const float*)d_in[10];
    const float* Wr_iu = (const float*)d_in[11];
    const float* W_user = (const float*)d_in[12];
    const float* b_user = (const float*)d_in[13];
    const float* W_item = (const float*)d_in[14];
    const float* b_item = (const float*)d_in[15];
    float* out = (float*)d_out;

    int ne_ui = in_sizes[2];
    int ne_iu = in_sizes[4];
    int totE = ne_ui + ne_iu;

    void *p_aggh, *p_aggl, *p_Wuh, *p_Wul, *p_Wih, *p_Wil, *p_cu, *p_ci;
    cudaGetSymbolAddress(&p_aggh, g_aggh);
    cudaGetSymbolAddress(&p_aggl, g_aggl);
    cudaGetSymbolAddress(&p_Wuh, g_WuT_hi);
    cudaGetSymbolAddress(&p_Wul, g_WuT_lo);
    cudaGetSymbolAddress(&p_Wih, g_WiT_hi);
    cudaGetSymbolAddress(&p_Wil, g_WiT_lo);
    cudaGetSymbolAddress(&p_cu, g_cu);
    cudaGetSymbolAddress(&p_ci, g_ci);

    cudaFuncSetAttribute(node_gemm_mma, cudaFuncAttributeMaxDynamicSharedMemorySize, SM_TOTAL);

    // CSR build: user-dst edges are (iu), item-dst edges are (ui) offset by NUU
    zero_cnt<<<(NT + 255) / 256, 256>>>();
    hist_k<<<(ne_iu + 255) / 256, 256>>>(edst_iu, ne_iu, 0);
    hist_k<<<(ne_ui + 255) / 256, 256>>>(edst_ui, ne_ui, NUU);
    scan1<<<NBLK, 1024>>>();
    scan2<<<1, 512>>>();
    scan3<<<NBLK, 1024>>>(totE);
    fill_k<<<(ne_iu + 255) / 256, 256>>>(esrc_iu, edst_iu, ne_iu, 0);
    fill_k<<<(ne_ui + 255) / 256, 256>>>(esrc_ui, edst_ui, ne_ui, NUU);

    combine_w<<<dim3(128, 4), 128>>>(Wl_iu, Wr_iu, Wl_ui, Wr_ui, W_user, W_item);
    combine_c<<<2, 128>>>(bl_iu, b_user, bl_ui, b_item, W_user, W_item);

    gather_k<<<(NT * 32 + 255) / 256, 256>>>(x_user, x_item);

    node_gemm_mma<<<(NUU + 127) / 128, 256, SM_TOTAL>>>(
        (const __nv_bfloat16*)p_aggh, (const __nv_bfloat16*)p_aggl, x_user,
        (const __nv_bfloat16*)p_Wuh, (const __nv_bfloat16*)p_Wul,
        (const float*)p_cu, out, NUU);
    node_gemm_mma<<<(NII + 127) / 128, 256, SM_TOTAL>>>(
        (const __nv_bfloat16*)p_aggh + (size_t)NUU * 128,
        (const __nv_bfloat16*)p_aggl + (size_t)NUU * 128, x_item,
        (const __nv_bfloat16*)p_Wih, (const __nv_bfloat16*)p_Wil,
        (const float*)p_ci, out + (size_t)NUU * 128, NII);
}